// round 1
// baseline (speedup 1.0000x reference)
#include <cuda_runtime.h>
#include <cuda_bf16.h>
#include <math.h>

#define BATCH   2
#define LSEQ    4096
#define NTOK    (BATCH*LSEQ)      // 8192
#define DMODEL  1024
#define DINNER  2048
#define NHEADS  32
#define HEADDIM 64
#define DSTATE  128
#define DCONV   4
#define CONVDIM (DINNER + 2*DSTATE)          // 2304
#define DINPROJ (2*DINNER + 2*DSTATE + NHEADS) // 4384

// ---------------- scratch (static device allocations, allowed) ----------------
__device__ float g_zx[NTOK * DINPROJ];   // in_proj output [token, 4384]
__device__ float g_xc[NTOK * DINNER];    // conv+silu x part
__device__ float g_Bc[NTOK * DSTATE];
__device__ float g_Cc[NTOK * DSTATE];
__device__ float g_dt[NTOK * NHEADS];    // softplus(dt + bias)
__device__ float g_da[NTOK * NHEADS];    // exp(A*dt) decay
__device__ float g_y [2 * NTOK * DINNER];// two state-halves of scan output
__device__ float g_g [NTOK * DINNER];    // gated+normed

// ---------------- fp32 tiled GEMM: C[M,N] = A[M,K] @ B[K,N] ----------------
// BM=BN=128, BK=8, 256 threads, 8x8 per thread. M % 128 == 0, K % 8 == 0 assumed.
__global__ __launch_bounds__(256, 2)
void sgemm128(const float* __restrict__ A, const float* __restrict__ B,
              float* __restrict__ C, int M, int N, int K)
{
    const int BM = 128, BN = 128, BK = 8;
    __shared__ float As[BK][BM];
    __shared__ float Bs[BK][BN];

    int tid = threadIdx.x;
    int bm = blockIdx.y * BM;
    int bn = blockIdx.x * BN;

    int arow = tid >> 1;           // 0..127
    int acol = (tid & 1) * 4;      // 0 or 4
    int brow = tid >> 5;           // 0..7
    int bcol = (tid & 31) * 4;     // 0..124

    int tx = tid & 15, ty = tid >> 4;

    float acc[8][8];
#pragma unroll
    for (int i = 0; i < 8; i++)
#pragma unroll
        for (int j = 0; j < 8; j++) acc[i][j] = 0.f;

    const float* Aptr = A + (size_t)(bm + arow) * K;

    for (int k0 = 0; k0 < K; k0 += BK) {
        // A tile (always in bounds)
        float4 av = *(const float4*)(Aptr + k0 + acol);
        As[acol + 0][arow] = av.x;
        As[acol + 1][arow] = av.y;
        As[acol + 2][arow] = av.z;
        As[acol + 3][arow] = av.w;
        // B tile (guard columns)
        {
            int gcol = bn + bcol;
            const float* Bp = B + (size_t)(k0 + brow) * N;
            if (gcol + 3 < N) {
                *(float4*)&Bs[brow][bcol] = *(const float4*)(Bp + gcol);
            } else {
#pragma unroll
                for (int j = 0; j < 4; j++)
                    Bs[brow][bcol + j] = (gcol + j < N) ? Bp[gcol + j] : 0.f;
            }
        }
        __syncthreads();

#pragma unroll
        for (int k = 0; k < BK; k++) {
            float ra[8], rb[8];
            *(float4*)(ra)     = *(const float4*)&As[k][ty * 8];
            *(float4*)(ra + 4) = *(const float4*)&As[k][ty * 8 + 4];
            *(float4*)(rb)     = *(const float4*)&Bs[k][tx * 8];
            *(float4*)(rb + 4) = *(const float4*)&Bs[k][tx * 8 + 4];
#pragma unroll
            for (int i = 0; i < 8; i++)
#pragma unroll
                for (int j = 0; j < 8; j++)
                    acc[i][j] = fmaf(ra[i], rb[j], acc[i][j]);
        }
        __syncthreads();
    }

#pragma unroll
    for (int i = 0; i < 8; i++) {
        size_t r = (size_t)(bm + ty * 8 + i) * N;
#pragma unroll
        for (int j = 0; j < 8; j += 4) {
            int cidx = bn + tx * 8 + j;
            if (cidx + 3 < N) {
                *(float4*)(C + r + cidx) =
                    make_float4(acc[i][j], acc[i][j+1], acc[i][j+2], acc[i][j+3]);
            } else {
#pragma unroll
                for (int q = 0; q < 4; q++)
                    if (cidx + q < N) C[r + cidx + q] = acc[i][j + q];
            }
        }
    }
}

// ---------------- conv + silu + dt softplus/decay ----------------
__device__ __forceinline__ float silu_f(float v) { return v / (1.f + expf(-v)); }

__global__ void conv_kernel(const float* __restrict__ conv_w,
                            const float* __restrict__ conv_b,
                            const float* __restrict__ dt_bias,
                            const float* __restrict__ A_log)
{
    int token = blockIdx.x;
    int l = token % LSEQ;

    for (int c = threadIdx.x; c < CONVDIM; c += blockDim.x) {
        float acc = conv_b[c];
#pragma unroll
        for (int d = 0; d < DCONV; d++) {
            if (l - d >= 0)
                acc = fmaf(conv_w[d * CONVDIM + c],
                           g_zx[(size_t)(token - d) * DINPROJ + DINNER + c], acc);
        }
        float s = silu_f(acc);
        if (c < DINNER)               g_xc[(size_t)token * DINNER + c] = s;
        else if (c < DINNER + DSTATE) g_Bc[(size_t)token * DSTATE + (c - DINNER)] = s;
        else                          g_Cc[(size_t)token * DSTATE + (c - DINNER - DSTATE)] = s;
    }
    for (int h = threadIdx.x; h < NHEADS; h += blockDim.x) {
        float raw = g_zx[(size_t)token * DINPROJ + DINNER + CONVDIM + h] + dt_bias[h];
        float sp = (raw > 20.f) ? raw : log1pf(expf(raw));
        g_dt[(size_t)token * NHEADS + h] = sp;
        g_da[(size_t)token * NHEADS + h] = expf(-expf(A_log[h]) * sp);
    }
}

// ---------------- selective scan ----------------
// grid = 128: blockIdx.x = (b*32 + h)*2 + half.  256 threads: p = tid>>2 (0..63),
// g = tid&3 -> 16 state cols each, n0 = half*64 + g*16. Chunked T=8 per barrier.
__global__ __launch_bounds__(256, 1)
void scan_kernel()
{
    const int T = 8;
    int half = blockIdx.x & 1;
    int bh   = blockIdx.x >> 1;
    int b = bh >> 5, h = bh & 31;

    int tid = threadIdx.x;
    int g = tid & 3;
    int p = tid >> 2;
    int n0 = half * 64 + g * 16;

    float st[16];
#pragma unroll
    for (int i = 0; i < 16; i++) st[i] = 0.f;

    __shared__ float sB[T][DSTATE];
    __shared__ float sC[T][DSTATE];
    __shared__ float sx[T][HEADDIM];
    __shared__ float sdt[T], sa[T];

    const int CH = 2 * DSTATE + HEADDIM; // 320
    size_t base_tok = (size_t)b * LSEQ;
    size_t yb = (size_t)half * NTOK * DINNER;

    for (int t0 = 0; t0 < LSEQ; t0 += T) {
        __syncthreads();
        for (int idx = tid; idx < T * CH; idx += 256) {
            int tt = idx / CH;
            int c  = idx % CH;
            size_t token = base_tok + t0 + tt;
            if (c < DSTATE)            sB[tt][c] = g_Bc[token * DSTATE + c];
            else if (c < 2 * DSTATE)   sC[tt][c - DSTATE] = g_Cc[token * DSTATE + (c - DSTATE)];
            else                       sx[tt][c - 2*DSTATE] =
                                           g_xc[token * DINNER + h * HEADDIM + (c - 2*DSTATE)];
        }
        if (tid < T) {
            size_t token = base_tok + t0 + tid;
            sdt[tid] = g_dt[token * NHEADS + h];
            sa[tid]  = g_da[token * NHEADS + h];
        }
        __syncthreads();

        for (int tt = 0; tt < T; tt++) {
            float a    = sa[tt];
            float coef = sx[tt][p] * sdt[tt];
            float y = 0.f;
            const float4* Bv = (const float4*)&sB[tt][n0];
            const float4* Cv = (const float4*)&sC[tt][n0];
#pragma unroll
            for (int i = 0; i < 4; i++) {
                float4 bb = Bv[i], cc = Cv[i];
                st[4*i+0] = fmaf(st[4*i+0], a, coef * bb.x); y = fmaf(st[4*i+0], cc.x, y);
                st[4*i+1] = fmaf(st[4*i+1], a, coef * bb.y); y = fmaf(st[4*i+1], cc.y, y);
                st[4*i+2] = fmaf(st[4*i+2], a, coef * bb.z); y = fmaf(st[4*i+2], cc.z, y);
                st[4*i+3] = fmaf(st[4*i+3], a, coef * bb.w); y = fmaf(st[4*i+3], cc.w, y);
            }
            // reduce over the 4 n-groups (low 2 lane bits)
            y += __shfl_xor_sync(0xffffffffu, y, 1);
            y += __shfl_xor_sync(0xffffffffu, y, 2);
            if (g == 0)
                g_y[yb + (base_tok + t0 + tt) * DINNER + h * HEADDIM + p] = y;
        }
    }
}

// ---------------- gate (silu(z)) + skip + RMSNorm ----------------
__global__ void gate_norm(const float* __restrict__ Dv,
                          const float* __restrict__ norm_w)
{
    int token = blockIdx.x;
    int tid = threadIdx.x; // 256
    __shared__ float red[8];
    __shared__ float rstd;

    float vals[8];
    float ss = 0.f;
#pragma unroll
    for (int i = 0; i < 8; i++) {
        int c = tid + i * 256;
        int h = c >> 6;
        float y = g_y[(size_t)token * DINNER + c]
                + g_y[(size_t)NTOK * DINNER + (size_t)token * DINNER + c]
                + g_xc[(size_t)token * DINNER + c] * Dv[h];
        float z = g_zx[(size_t)token * DINPROJ + c];
        float gg = y * silu_f(z);
        vals[i] = gg;
        ss = fmaf(gg, gg, ss);
    }
#pragma unroll
    for (int o = 16; o > 0; o >>= 1) ss += __shfl_xor_sync(0xffffffffu, ss, o);
    if ((tid & 31) == 0) red[tid >> 5] = ss;
    __syncthreads();
    if (tid == 0) {
        float s = 0.f;
#pragma unroll
        for (int i = 0; i < 8; i++) s += red[i];
        rstd = rsqrtf(s / (float)DINNER + 1e-5f);
    }
    __syncthreads();
    float r = rstd;
#pragma unroll
    for (int i = 0; i < 8; i++) {
        int c = tid + i * 256;
        g_g[(size_t)token * DINNER + c] = vals[i] * r * norm_w[c];
    }
}

// ---------------- launcher ----------------
extern "C" void kernel_launch(void* const* d_in, const int* in_sizes, int n_in,
                              void* d_out, int out_size)
{
    const float* x          = (const float*)d_in[0];
    const float* in_proj_w  = (const float*)d_in[1];
    const float* conv_w     = (const float*)d_in[2];
    const float* conv_b     = (const float*)d_in[3];
    const float* norm_w     = (const float*)d_in[4];
    const float* out_proj_w = (const float*)d_in[5];
    const float* dt_bias    = (const float*)d_in[6];
    const float* A_log      = (const float*)d_in[7];
    const float* Dv         = (const float*)d_in[8];
    float* out = (float*)d_out;

    float *zx_p, *g_p;
    cudaGetSymbolAddress((void**)&zx_p, g_zx);
    cudaGetSymbolAddress((void**)&g_p,  g_g);

    // 1) in_proj: [8192,1024] @ [1024,4384]
    dim3 grid1((DINPROJ + 127) / 128, NTOK / 128);
    sgemm128<<<grid1, 256>>>(x, in_proj_w, zx_p, NTOK, DINPROJ, DMODEL);

    // 2) conv + silu + dt transforms
    conv_kernel<<<NTOK, 256>>>(conv_w, conv_b, dt_bias, A_log);

    // 3) selective scan (2 state-halves per (b,h))
    scan_kernel<<<BATCH * NHEADS * 2, 256>>>();

    // 4) gate + skip + RMSNorm
    gate_norm<<<NTOK, 256>>>(Dv, norm_w);

    // 5) out_proj: [8192,2048] @ [2048,1024]
    dim3 grid2(DMODEL / 128, NTOK / 128);
    sgemm128<<<grid2, 256>>>(g_p, out_proj_w, out, NTOK, DMODEL, DINNER);
}

// round 3
// speedup vs baseline: 1.3830x; 1.3830x over previous
#include <cuda_runtime.h>
#include <cuda_bf16.h>
#include <math.h>
#include <stdint.h>

#define BATCH   2
#define LSEQ    4096
#define NTOK    (BATCH*LSEQ)      // 8192
#define DMODEL  1024
#define DINNER  2048
#define NHEADS  32
#define HEADDIM 64
#define DSTATE  128
#define DCONV   4
#define CONVDIM (DINNER + 2*DSTATE)            // 2304
#define DINPROJ (2*DINNER + 2*DSTATE + NHEADS) // 4384
#define NPAD1   4480                           // 35*128

// ---------------- scratch ----------------
__device__ float g_zx[NTOK * DINPROJ];
__device__ float g_xc[NTOK * DINNER];
__device__ float g_Bc[NTOK * DSTATE];
__device__ float g_Cc[NTOK * DSTATE];
__device__ float g_dt[NTOK * NHEADS];
__device__ float g_da[NTOK * NHEADS];
__device__ float g_y [2 * NTOK * DINNER];

__device__ __nv_bfloat16 s_xh[NTOK * DMODEL];
__device__ __nv_bfloat16 s_xl[NTOK * DMODEL];
__device__ __nv_bfloat16 s_w1h[NPAD1 * DMODEL];
__device__ __nv_bfloat16 s_w1l[NPAD1 * DMODEL];
__device__ __nv_bfloat16 s_gh[NTOK * DINNER];
__device__ __nv_bfloat16 s_gl[NTOK * DINNER];
__device__ __nv_bfloat16 s_w2h[DMODEL * DINNER];  // [1024][2048]
__device__ __nv_bfloat16 s_w2l[DMODEL * DINNER];

// ---------------- PTX helpers (baseline sm_80+ instructions only) ----------------
__device__ __forceinline__ uint32_t smem_u32(const void* p) {
    uint32_t a;
    asm("{ .reg .u64 t; cvta.to.shared.u64 t, %1; cvt.u32.u64 %0, t; }" : "=r"(a) : "l"(p));
    return a;
}
__device__ __forceinline__ void cpasync16(uint32_t dst, const void* src) {
    asm volatile("cp.async.cg.shared.global [%0], [%1], 16;" :: "r"(dst), "l"(src));
}
#define CP_COMMIT() asm volatile("cp.async.commit_group;" ::: "memory")
#define CP_WAIT1()  asm volatile("cp.async.wait_group 1;"  ::: "memory")
#define CP_WAIT0()  asm volatile("cp.async.wait_group 0;"  ::: "memory")

__device__ __forceinline__ void ldsm4(uint32_t* r, uint32_t addr) {
    asm volatile("ldmatrix.sync.aligned.m8n8.x4.shared.b16 {%0,%1,%2,%3}, [%4];"
                 : "=r"(r[0]), "=r"(r[1]), "=r"(r[2]), "=r"(r[3]) : "r"(addr));
}
__device__ __forceinline__ void mma16816(float* c, const uint32_t* a, const uint32_t* b) {
    asm volatile(
        "mma.sync.aligned.m16n8k16.row.col.f32.bf16.bf16.f32 "
        "{%0,%1,%2,%3}, {%4,%5,%6,%7}, {%8,%9}, {%0,%1,%2,%3};"
        : "+f"(c[0]), "+f"(c[1]), "+f"(c[2]), "+f"(c[3])
        : "r"(a[0]), "r"(a[1]), "r"(a[2]), "r"(a[3]), "r"(b[0]), "r"(b[1]));
}

// ---------------- bf16 hi/lo split helpers ----------------
__device__ __forceinline__ void split_bf16(float v, __nv_bfloat16& h, __nv_bfloat16& l) {
    h = __float2bfloat16(v);
    l = __float2bfloat16(v - __bfloat162float(h));
}

// Elementwise split (row-major, no transpose). n4 = elems/4.
__global__ void split_rows(const float* __restrict__ X,
                           __nv_bfloat16* __restrict__ H,
                           __nv_bfloat16* __restrict__ L, int n4)
{
    int i = blockIdx.x * blockDim.x + threadIdx.x;
    if (i >= n4) return;
    float4 v = ((const float4*)X)[i];
    __nv_bfloat16 h0, h1, h2, h3, l0, l1, l2, l3;
    split_bf16(v.x, h0, l0); split_bf16(v.y, h1, l1);
    split_bf16(v.z, h2, l2); split_bf16(v.w, h3, l3);
    uint2 hv, lv;
    hv.x = ((uint32_t)__bfloat16_as_ushort(h1) << 16) | __bfloat16_as_ushort(h0);
    hv.y = ((uint32_t)__bfloat16_as_ushort(h3) << 16) | __bfloat16_as_ushort(h2);
    lv.x = ((uint32_t)__bfloat16_as_ushort(l1) << 16) | __bfloat16_as_ushort(l0);
    lv.y = ((uint32_t)__bfloat16_as_ushort(l3) << 16) | __bfloat16_as_ushort(l2);
    ((uint2*)H)[i] = hv;
    ((uint2*)L)[i] = lv;
}

// W[K][N] fp32 -> Th/Tl [Npad][K] bf16 (transpose + split; pad rows zero)
__global__ void split_transpose(const float* __restrict__ W,
                                __nv_bfloat16* __restrict__ Th,
                                __nv_bfloat16* __restrict__ Tl, int K, int N)
{
    __shared__ float t[32][33];
    int n0 = blockIdx.x * 32, k0 = blockIdx.y * 32;
    int tx = threadIdx.x, ty = threadIdx.y;  // 32 x 8
#pragma unroll
    for (int dy = 0; dy < 32; dy += 8) {
        int k = k0 + ty + dy, n = n0 + tx;
        t[ty + dy][tx] = (n < N) ? W[(size_t)k * N + n] : 0.f;
    }
    __syncthreads();
#pragma unroll
    for (int dy = 0; dy < 32; dy += 8) {
        int n = n0 + ty + dy, k = k0 + tx;
        float v = t[tx][ty + dy];
        __nv_bfloat16 h, l;
        split_bf16(v, h, l);
        Th[(size_t)n * K + k] = h;
        Tl[(size_t)n * K + k] = l;
    }
}

// ---------------- bf16 split-GEMM (warp mma.sync): C[M,N] = A[M,K] @ B^T ----------------
// A: [M][K] bf16 hi/lo, B: [Npad][K] bf16 hi/lo (n-major). Tile 128x128x64.
#define GBM 128
#define GBN 128
#define GBK 64
#define GSTAGE 65536
#define GSMEM  (2 * GSTAGE)

__global__ __launch_bounds__(256, 1)
void hgemm(const __nv_bfloat16* __restrict__ Ah, const __nv_bfloat16* __restrict__ Al,
           const __nv_bfloat16* __restrict__ Bh, const __nv_bfloat16* __restrict__ Bl,
           float* __restrict__ C, int M, int N, int K)
{
    extern __shared__ char smem[];
    uint32_t sb = smem_u32(smem);
    int tid = threadIdx.x, lane = tid & 31, wid = tid >> 5;
    int bm = blockIdx.y * GBM, bn = blockIdx.x * GBN;
    int mwarp = (wid & 1) * 64, nwarp = (wid >> 1) * 32;

    float acc[4][4][4];
#pragma unroll
    for (int i = 0; i < 4; i++)
#pragma unroll
        for (int j = 0; j < 4; j++)
#pragma unroll
            for (int q = 0; q < 4; q++) acc[i][j][q] = 0.f;

    int sub = lane >> 3, r8 = lane & 7;
    int a_ro = ((sub & 1) << 3) + r8, a_co = sub >> 1;
    int b_ro = ((sub >> 1) << 3) + r8, b_co = sub & 1;

    const __nv_bfloat16* bases[4] = {
        Ah + (size_t)bm * K, Al + (size_t)bm * K,
        Bh + (size_t)bn * K, Bl + (size_t)bn * K };

    const int nchunk = K / GBK;

    auto load_stage = [&](int c, int stage) {
        int k0 = c * GBK;
        uint32_t sbase = sb + stage * GSTAGE;
#pragma unroll
        for (int buf = 0; buf < 4; buf++) {
            const __nv_bfloat16* base = bases[buf] + k0;
#pragma unroll
            for (int q = 0; q < 4; q++) {
                int idx = tid + q * 256;        // 0..1023
                int r = idx >> 3, c16 = idx & 7;
                uint32_t dst = sbase + buf * 16384 + r * 128 + ((c16 ^ (r & 7)) << 4);
                cpasync16(dst, base + (size_t)r * K + c16 * 8);
            }
        }
        CP_COMMIT();
    };

    load_stage(0, 0);

    for (int c = 0; c < nchunk; ++c) {
        int stage = c & 1;
        if (c + 1 < nchunk) { load_stage(c + 1, stage ^ 1); CP_WAIT1(); }
        else                { CP_WAIT0(); }
        __syncthreads();

        uint32_t abase = sb + stage * GSTAGE;
#pragma unroll
        for (int ks = 0; ks < 4; ks++) {
            uint32_t ah[4][4], al[4][4], bh[4][2], bl[4][2];
#pragma unroll
            for (int i = 0; i < 4; i++) {
                int row = mwarp + i * 16 + a_ro;
                int c16 = ks * 2 + a_co;
                uint32_t off = row * 128 + ((c16 ^ (row & 7)) << 4);
                ldsm4(ah[i], abase + off);
                ldsm4(al[i], abase + 16384 + off);
            }
#pragma unroll
            for (int j2 = 0; j2 < 2; j2++) {
                int row = nwarp + j2 * 16 + b_ro;
                int c16 = ks * 2 + b_co;
                uint32_t off = row * 128 + ((c16 ^ (row & 7)) << 4);
                uint32_t rh[4], rl[4];
                ldsm4(rh, abase + 32768 + off);
                ldsm4(rl, abase + 49152 + off);
                bh[j2*2][0] = rh[0]; bh[j2*2][1] = rh[1];
                bh[j2*2+1][0] = rh[2]; bh[j2*2+1][1] = rh[3];
                bl[j2*2][0] = rl[0]; bl[j2*2][1] = rl[1];
                bl[j2*2+1][0] = rl[2]; bl[j2*2+1][1] = rl[3];
            }
#pragma unroll
            for (int i = 0; i < 4; i++)
#pragma unroll
                for (int j = 0; j < 4; j++) {
                    mma16816(acc[i][j], ah[i], bh[j]);
                    mma16816(acc[i][j], ah[i], bl[j]);
                    mma16816(acc[i][j], al[i], bh[j]);
                }
        }
        __syncthreads();
    }

    // epilogue: direct float2 stores
    int g = lane >> 2, tg = lane & 3;
#pragma unroll
    for (int i = 0; i < 4; i++) {
#pragma unroll
        for (int j = 0; j < 4; j++) {
            int m = bm + mwarp + i * 16 + g;
            int n = bn + nwarp + j * 8 + tg * 2;
            if (n < N) {
                float2 v0 = make_float2(acc[i][j][0], acc[i][j][1]);
                float2 v1 = make_float2(acc[i][j][2], acc[i][j][3]);
                *(float2*)(C + (size_t)m * N + n) = v0;
                *(float2*)(C + (size_t)(m + 8) * N + n) = v1;
            }
        }
    }
}

// ---------------- conv + silu + dt softplus/decay ----------------
__device__ __forceinline__ float silu_f(float v) { return v / (1.f + expf(-v)); }

__global__ void conv_kernel(const float* __restrict__ conv_w,
                            const float* __restrict__ conv_b,
                            const float* __restrict__ dt_bias,
                            const float* __restrict__ A_log)
{
    int token = blockIdx.x;
    int l = token % LSEQ;

    for (int c = threadIdx.x; c < CONVDIM; c += blockDim.x) {
        float acc = conv_b[c];
#pragma unroll
        for (int d = 0; d < DCONV; d++) {
            if (l - d >= 0)
                acc = fmaf(conv_w[d * CONVDIM + c],
                           g_zx[(size_t)(token - d) * DINPROJ + DINNER + c], acc);
        }
        float s = silu_f(acc);
        if (c < DINNER)               g_xc[(size_t)token * DINNER + c] = s;
        else if (c < DINNER + DSTATE) g_Bc[(size_t)token * DSTATE + (c - DINNER)] = s;
        else                          g_Cc[(size_t)token * DSTATE + (c - DINNER - DSTATE)] = s;
    }
    for (int h = threadIdx.x; h < NHEADS; h += blockDim.x) {
        float raw = g_zx[(size_t)token * DINPROJ + DINNER + CONVDIM + h] + dt_bias[h];
        float sp = (raw > 20.f) ? raw : log1pf(expf(raw));
        g_dt[(size_t)token * NHEADS + h] = sp;
        g_da[(size_t)token * NHEADS + h] = expf(-expf(A_log[h]) * sp);
    }
}

// ---------------- selective scan ----------------
__global__ __launch_bounds__(256, 1)
void scan_kernel()
{
    const int T = 8;
    int half = blockIdx.x & 1;
    int bh   = blockIdx.x >> 1;
    int b = bh >> 5, h = bh & 31;

    int tid = threadIdx.x;
    int g = tid & 3;
    int p = tid >> 2;
    int n0 = half * 64 + g * 16;

    float st[16];
#pragma unroll
    for (int i = 0; i < 16; i++) st[i] = 0.f;

    __shared__ float sB[T][DSTATE];
    __shared__ float sC[T][DSTATE];
    __shared__ float sx[T][HEADDIM];
    __shared__ float sdt[T], sa[T];

    const int CH = 2 * DSTATE + HEADDIM;
    size_t base_tok = (size_t)b * LSEQ;
    size_t yb = (size_t)half * NTOK * DINNER;

    for (int t0 = 0; t0 < LSEQ; t0 += T) {
        __syncthreads();
        for (int idx = tid; idx < T * CH; idx += 256) {
            int tt = idx / CH;
            int c  = idx % CH;
            size_t token = base_tok + t0 + tt;
            if (c < DSTATE)            sB[tt][c] = g_Bc[token * DSTATE + c];
            else if (c < 2 * DSTATE)   sC[tt][c - DSTATE] = g_Cc[token * DSTATE + (c - DSTATE)];
            else                       sx[tt][c - 2*DSTATE] =
                                           g_xc[token * DINNER + h * HEADDIM + (c - 2*DSTATE)];
        }
        if (tid < T) {
            size_t token = base_tok + t0 + tid;
            sdt[tid] = g_dt[token * NHEADS + h];
            sa[tid]  = g_da[token * NHEADS + h];
        }
        __syncthreads();

        for (int tt = 0; tt < T; tt++) {
            float a    = sa[tt];
            float coef = sx[tt][p] * sdt[tt];
            float y = 0.f;
            const float4* Bv = (const float4*)&sB[tt][n0];
            const float4* Cv = (const float4*)&sC[tt][n0];
#pragma unroll
            for (int i = 0; i < 4; i++) {
                float4 bb = Bv[i], cc = Cv[i];
                st[4*i+0] = fmaf(st[4*i+0], a, coef * bb.x); y = fmaf(st[4*i+0], cc.x, y);
                st[4*i+1] = fmaf(st[4*i+1], a, coef * bb.y); y = fmaf(st[4*i+1], cc.y, y);
                st[4*i+2] = fmaf(st[4*i+2], a, coef * bb.z); y = fmaf(st[4*i+2], cc.z, y);
                st[4*i+3] = fmaf(st[4*i+3], a, coef * bb.w); y = fmaf(st[4*i+3], cc.w, y);
            }
            y += __shfl_xor_sync(0xffffffffu, y, 1);
            y += __shfl_xor_sync(0xffffffffu, y, 2);
            if (g == 0)
                g_y[yb + (base_tok + t0 + tt) * DINNER + h * HEADDIM + p] = y;
        }
    }
}

// ---------------- gate + skip + RMSNorm (emits bf16 hi/lo for out_proj) ----------------
__global__ void gate_norm(const float* __restrict__ Dv,
                          const float* __restrict__ norm_w)
{
    int token = blockIdx.x;
    int tid = threadIdx.x;
    __shared__ float red[8];
    __shared__ float rstd;

    float vals[8];
    float ss = 0.f;
#pragma unroll
    for (int i = 0; i < 8; i++) {
        int c = tid + i * 256;
        int h = c >> 6;
        float y = g_y[(size_t)token * DINNER + c]
                + g_y[(size_t)NTOK * DINNER + (size_t)token * DINNER + c]
                + g_xc[(size_t)token * DINNER + c] * Dv[h];
        float z = g_zx[(size_t)token * DINPROJ + c];
        float gg = y * silu_f(z);
        vals[i] = gg;
        ss = fmaf(gg, gg, ss);
    }
#pragma unroll
    for (int o = 16; o > 0; o >>= 1) ss += __shfl_xor_sync(0xffffffffu, ss, o);
    if ((tid & 31) == 0) red[tid >> 5] = ss;
    __syncthreads();
    if (tid == 0) {
        float s = 0.f;
#pragma unroll
        for (int i = 0; i < 8; i++) s += red[i];
        rstd = rsqrtf(s / (float)DINNER + 1e-5f);
    }
    __syncthreads();
    float r = rstd;
#pragma unroll
    for (int i = 0; i < 8; i++) {
        int c = tid + i * 256;
        float o = vals[i] * r * norm_w[c];
        __nv_bfloat16 h, l;
        split_bf16(o, h, l);
        s_gh[(size_t)token * DINNER + c] = h;
        s_gl[(size_t)token * DINNER + c] = l;
    }
}

// ---------------- launcher ----------------
extern "C" void kernel_launch(void* const* d_in, const int* in_sizes, int n_in,
                              void* d_out, int out_size)
{
    const float* x          = (const float*)d_in[0];
    const float* in_proj_w  = (const float*)d_in[1];
    const float* conv_w     = (const float*)d_in[2];
    const float* conv_b     = (const float*)d_in[3];
    const float* norm_w     = (const float*)d_in[4];
    const float* out_proj_w = (const float*)d_in[5];
    const float* dt_bias    = (const float*)d_in[6];
    const float* A_log      = (const float*)d_in[7];
    const float* Dv         = (const float*)d_in[8];
    float* out = (float*)d_out;

    float* zx_p;
    __nv_bfloat16 *xh_p, *xl_p, *w1h_p, *w1l_p, *gh_p, *gl_p, *w2h_p, *w2l_p;
    cudaGetSymbolAddress((void**)&zx_p,  g_zx);
    cudaGetSymbolAddress((void**)&xh_p,  s_xh);
    cudaGetSymbolAddress((void**)&xl_p,  s_xl);
    cudaGetSymbolAddress((void**)&w1h_p, s_w1h);
    cudaGetSymbolAddress((void**)&w1l_p, s_w1l);
    cudaGetSymbolAddress((void**)&gh_p,  s_gh);
    cudaGetSymbolAddress((void**)&gl_p,  s_gl);
    cudaGetSymbolAddress((void**)&w2h_p, s_w2h);
    cudaGetSymbolAddress((void**)&w2l_p, s_w2l);

    cudaFuncSetAttribute(hgemm, cudaFuncAttributeMaxDynamicSharedMemorySize, GSMEM);

    // 0) splits
    split_rows<<<(NTOK * DMODEL / 4 + 255) / 256, 256>>>(x, xh_p, xl_p, NTOK * DMODEL / 4);
    split_transpose<<<dim3(NPAD1 / 32, DMODEL / 32), dim3(32, 8)>>>(in_proj_w, w1h_p, w1l_p, DMODEL, DINPROJ);
    split_transpose<<<dim3(DMODEL / 32, DINNER / 32), dim3(32, 8)>>>(out_proj_w, w2h_p, w2l_p, DINNER, DMODEL);

    // 1) in_proj: [8192,1024] @ [1024,4384]
    hgemm<<<dim3(NPAD1 / GBN, NTOK / GBM), 256, GSMEM>>>(xh_p, xl_p, w1h_p, w1l_p,
                                                         zx_p, NTOK, DINPROJ, DMODEL);

    // 2) conv + silu + dt transforms
    conv_kernel<<<NTOK, 256>>>(conv_w, conv_b, dt_bias, A_log);

    // 3) selective scan
    scan_kernel<<<BATCH * NHEADS * 2, 256>>>();

    // 4) gate + skip + RMSNorm -> bf16 hi/lo
    gate_norm<<<NTOK, 256>>>(Dv, norm_w);

    // 5) out_proj: [8192,2048] @ [2048,1024]
    hgemm<<<dim3(DMODEL / GBN, NTOK / GBM), 256, GSMEM>>>(gh_p, gl_p, w2h_p, w2l_p,
                                                          out, NTOK, DMODEL, DINNER);
}